// round 1
// baseline (speedup 1.0000x reference)
#include <cuda_runtime.h>
#include <math.h>
#include <stdint.h>

// Problem constants (fixed by the dataset)
#define U_   2048
#define I_   16384
#define NN_  18432
#define F_   64
#define H_   32
#define EMAX 1000000
#define TOPK_ 3

// ---------------- device scratch (static globals; no dynamic alloc) -------
__device__ int   g_cnt_u[U_];
__device__ int   g_cnt_i[I_];
__device__ int   g_cursor[I_];
__device__ int   g_off[I_ + 1];
__device__ float g_du[U_];
__device__ float g_di[I_];
__device__ float g_Dh[U_];
__device__ float g_Pu[U_ * H_];
__device__ float g_Pi[I_ * H_];
__device__ uint2 g_csr[EMAX];          // {user, float_bits(weight)} grouped by item
__device__ float g_C[U_ * U_];         // strict-upper-ish accumulation (unordered pairs)
__device__ float g_diag[U_];           // sum of w^2 terms per user

// ---------------- kernel 1: zero everything that needs zeroing ------------
__global__ void k_zero(float* outS) {
    int idx = blockIdx.x * blockDim.x + threadIdx.x;
    int stride = gridDim.x * blockDim.x;
    for (int i = idx; i < U_ * U_; i += stride) { g_C[i] = 0.0f; outS[i] = 0.0f; }
    for (int i = idx; i < I_; i += stride) { g_cnt_i[i] = 0; g_cursor[i] = 0; }
    if (idx < U_) { g_cnt_u[idx] = 0; g_diag[idx] = 0.0f; }
}

// ---------------- kernel 2: degree histograms ------------------------------
__global__ void k_degree(const int* __restrict__ src, const int* __restrict__ dst, int E) {
    int e = blockIdx.x * blockDim.x + threadIdx.x;
    if (e < E) {
        atomicAdd(&g_cnt_u[src[e]], 1);
        atomicAdd(&g_cnt_i[dst[e]], 1);
    }
}

// ---------------- kernel 3: log1p degrees, Dh, emit d_u output -------------
__global__ void k_findeg(float* __restrict__ out_du, int write_du) {
    int idx = blockIdx.x * blockDim.x + threadIdx.x;
    if (idx < U_) {
        float du = log1pf((float)g_cnt_u[idx]);
        g_du[idx] = du;
        g_Dh[idx] = sqrtf(du);
        if (write_du) out_du[idx] = du;
    }
    if (idx < I_) {
        g_di[idx] = log1pf((float)g_cnt_i[idx]);
    }
}

// ---------------- kernel 4: exclusive scan of item counts (1 block) --------
__global__ void k_scan() {
    __shared__ int sums[1024];
    int t = threadIdx.x;
    const int PER = I_ / 1024;      // 16
    int base = t * PER;
    int local[PER];
    int s = 0;
    #pragma unroll
    for (int j = 0; j < PER; j++) { local[j] = s; s += g_cnt_i[base + j]; }
    sums[t] = s;
    __syncthreads();
    // Hillis-Steele inclusive scan over thread sums
    for (int off = 1; off < 1024; off <<= 1) {
        int v = (t >= off) ? sums[t - off] : 0;
        __syncthreads();
        sums[t] += v;
        __syncthreads();
    }
    int prefix = (t == 0) ? 0 : sums[t - 1];
    #pragma unroll
    for (int j = 0; j < PER; j++) g_off[base + j] = prefix + local[j];
    if (t == 1023) g_off[I_] = sums[1023];
}

// ---------------- kernel 5: per-node projections through w1 ----------------
// One warp per node; lane = hidden unit h (H_ == 32).
__global__ void k_proj(const float* __restrict__ x, const float* __restrict__ w1,
                       const float* __restrict__ b1) {
    __shared__ float sw1[H_ * 130];
    for (int i = threadIdx.x; i < H_ * 130; i += blockDim.x) sw1[i] = w1[i];
    __syncthreads();
    int warp = blockIdx.x * (blockDim.x >> 5) + (threadIdx.x >> 5);
    int lane = threadIdx.x & 31;
    if (warp >= NN_) return;
    const float* xr = x + (size_t)warp * F_;
    bool is_user = (warp < U_);
    const float* wr = sw1 + lane * 130 + (is_user ? 0 : 65);
    float acc = 0.0f;
    #pragma unroll
    for (int f = 0; f < F_; f++) acc = fmaf(xr[f], wr[f], acc);
    if (is_user) {
        acc += g_du[warp] * sw1[lane * 130 + 64] + b1[lane];
        g_Pu[warp * H_ + lane] = acc;
    } else {
        int i = warp - U_;
        acc += g_di[i] * sw1[lane * 130 + 129];
        g_Pi[i * H_ + lane] = acc;
    }
}

// ---------------- kernel 6: per-edge weight + CSR scatter -------------------
__global__ void k_edge(const int* __restrict__ src, const int* __restrict__ dst,
                       const float* __restrict__ w2, const float* __restrict__ b2, int E) {
    __shared__ float sw2[H_];
    __shared__ float sb2;
    if (threadIdx.x < H_) sw2[threadIdx.x] = w2[threadIdx.x];
    if (threadIdx.x == 0) sb2 = b2[0];
    __syncthreads();
    int e = blockIdx.x * blockDim.x + threadIdx.x;
    if (e >= E) return;
    int u  = src[e];
    int it = dst[e];
    const float4* pu = (const float4*)(g_Pu + (size_t)u * H_);
    const float4* pi = (const float4*)(g_Pi + (size_t)it * H_);
    float s = 0.0f;
    #pragma unroll
    for (int j = 0; j < H_ / 4; j++) {
        float4 a = pu[j];
        float4 b = pi[j];
        s = fmaf(fmaxf(a.x + b.x, 0.0f), sw2[4 * j + 0], s);
        s = fmaf(fmaxf(a.y + b.y, 0.0f), sw2[4 * j + 1], s);
        s = fmaf(fmaxf(a.z + b.z, 0.0f), sw2[4 * j + 2], s);
        s = fmaf(fmaxf(a.w + b.w, 0.0f), sw2[4 * j + 3], s);
    }
    float w = 1.0f / (1.0f + expf(-(s + sb2)));
    int pos = g_off[it] + atomicAdd(&g_cursor[it], 1);
    if (pos < EMAX) g_csr[pos] = make_uint2((unsigned)u, __float_as_uint(w));
}

// ---------------- kernel 7: triangular pair products (the hot kernel) ------
// Block = one item. Warp w handles "a" rows a = w, w+8, ...; lanes sweep b >= a.
// b == a contributes w_a^2 to g_diag; b > a contributes to one direction of C.
__global__ void k_pairs() {
    int t = blockIdx.x;
    int base = g_off[t];
    int k = g_off[t + 1] - base;
    if (k <= 0) return;
    int warp = threadIdx.x >> 5;
    int lane = threadIdx.x & 31;
    for (int a = warp; a < k; a += 8) {
        uint2 ea = g_csr[base + a];        // broadcast load
        float wa = __uint_as_float(ea.y);
        float* Crow = g_C + (size_t)ea.x * U_;
        for (int b = a + lane; b < k; b += 32) {
            uint2 eb = g_csr[base + b];
            float v = wa * __uint_as_float(eb.y);
            if (b == a) atomicAdd(&g_diag[ea.x], v);
            else        atomicAdd(&Crow[eb.x], v);
        }
    }
}

// ---------------- kernel 8: symmetrize + scale + top-3 + scatter S ---------
__device__ __forceinline__ bool better(float v, int i, float bv, int bi) {
    return (v > bv) || (v == bv && (unsigned)i < (unsigned)bi);
}
__device__ __forceinline__ void ins3(float v, int i,
                                     float& v0, int& i0, float& v1, int& i1,
                                     float& v2, int& i2) {
    if (better(v, i, v0, i0)) { v2 = v1; i2 = i1; v1 = v0; i1 = i0; v0 = v; i0 = i; }
    else if (better(v, i, v1, i1)) { v2 = v1; i2 = i1; v1 = v; i1 = i; }
    else if (better(v, i, v2, i2)) { v2 = v; i2 = i; }
}

__global__ void k_topk(float* __restrict__ outS) {
    __shared__ float svals[256 * 3];
    __shared__ int   sidx[256 * 3];
    int r = blockIdx.x;
    float dhr = g_Dh[r];
    float v0 = -1.0f, v1 = -1.0f, v2 = -1.0f;
    int   i0 = -1,    i1 = -1,    i2 = -1;
    for (int c = threadIdx.x; c < U_; c += blockDim.x) {
        float v = g_C[(size_t)r * U_ + c] + g_C[(size_t)c * U_ + r];
        if (c == r) v += g_diag[r];
        v *= dhr * g_Dh[c];
        if (v > 0.0f) ins3(v, c, v0, i0, v1, i1, v2, i2);
    }
    int t = threadIdx.x;
    svals[t * 3 + 0] = v0; sidx[t * 3 + 0] = i0;
    svals[t * 3 + 1] = v1; sidx[t * 3 + 1] = i1;
    svals[t * 3 + 2] = v2; sidx[t * 3 + 2] = i2;
    __syncthreads();
    if (t < 32) {
        float m0 = -1.0f, m1 = -1.0f, m2 = -1.0f;
        int   j0 = -1,    j1 = -1,    j2 = -1;
        for (int j = t; j < 256; j += 32) {
            #pragma unroll
            for (int q = 0; q < 3; q++) {
                float v = svals[j * 3 + q];
                if (v > 0.0f) ins3(v, sidx[j * 3 + q], m0, j0, m1, j1, m2, j2);
            }
        }
        #pragma unroll
        for (int off = 16; off > 0; off >>= 1) {
            float ov0 = __shfl_down_sync(0xffffffffu, m0, off);
            float ov1 = __shfl_down_sync(0xffffffffu, m1, off);
            float ov2 = __shfl_down_sync(0xffffffffu, m2, off);
            int   oi0 = __shfl_down_sync(0xffffffffu, j0, off);
            int   oi1 = __shfl_down_sync(0xffffffffu, j1, off);
            int   oi2 = __shfl_down_sync(0xffffffffu, j2, off);
            if (ov0 > 0.0f) ins3(ov0, oi0, m0, j0, m1, j1, m2, j2);
            if (ov1 > 0.0f) ins3(ov1, oi1, m0, j0, m1, j1, m2, j2);
            if (ov2 > 0.0f) ins3(ov2, oi2, m0, j0, m1, j1, m2, j2);
        }
        if (t == 0) {
            float mv[3] = {m0, m1, m2};
            int   mi[3] = {j0, j1, j2};
            #pragma unroll
            for (int q = 0; q < 3; q++) {
                if (mv[q] > 0.0f) {
                    float vh = 0.5f * mv[q];
                    atomicAdd(&outS[(size_t)r * U_ + mi[q]], vh);
                    atomicAdd(&outS[(size_t)mi[q] * U_ + r], vh);
                }
            }
        }
    }
}

// ---------------------------------------------------------------------------
extern "C" void kernel_launch(void* const* d_in, const int* in_sizes, int n_in,
                              void* d_out, int out_size) {
    const float* x   = (const float*)d_in[0];
    const float* w1  = (const float*)d_in[1];
    const float* b1  = (const float*)d_in[2];
    const float* w2  = (const float*)d_in[3];
    const float* b2  = (const float*)d_in[4];
    const int*   src = (const int*)d_in[5];
    const int*   dst = (const int*)d_in[6];
    int E = in_sizes[5];
    if (E > EMAX) E = EMAX;

    float* outS = (float*)d_out;
    int write_du = (out_size >= U_ * U_ + U_) ? 1 : 0;

    k_zero<<<2048, 256>>>(outS);
    k_degree<<<(E + 255) / 256, 256>>>(src, dst, E);
    k_findeg<<<(I_ + 255) / 256, 256>>>(outS + (size_t)U_ * U_, write_du);
    k_scan<<<1, 1024>>>();
    k_proj<<<(NN_ + 7) / 8, 256>>>(x, w1, b1);
    k_edge<<<(E + 255) / 256, 256>>>(src, dst, w2, b2, E);
    k_pairs<<<I_, 256>>>();
    k_topk<<<U_, 256>>>(outS);
}